// round 1
// baseline (speedup 1.0000x reference)
#include <cuda_runtime.h>
#include <math.h>

#define N_   20000
#define E_   320000
#define M_   3
#define IN_  128
#define H_   4
#define D_   64
#define HD_  256
#define HID_ 128
#define NEG_SLOPE 0.2f

// ---------------- scratch (device globals: allocation-free) ----------------
__device__ __align__(16) float g_feat[M_*N_*HD_];   // [m][n][hd]
__device__ __align__(16) float g_z   [M_*N_*HD_];   // [m][n][hd]  (GAT out + bias)
__device__ __align__(16) float g_hid [M_*N_*HID_];  // tanh(z@W1+b1)
__device__ __align__(16) float g_ee  [M_*E_*H_];    // exp(leaky(el+er))
__device__ __align__(16) float g_el  [M_*N_*H_];
__device__ __align__(16) float g_er  [M_*N_*H_];
__device__ float g_denom[M_*N_*H_];
__device__ int   g_deg   [M_*N_];
__device__ int   g_rowptr[M_*(N_+1)];
__device__ int   g_cursor[M_*N_];
__device__ int   g_eidx  [M_*E_];
__device__ float g_wsum  [M_];
__device__ float g_beta  [M_];

// ---------------- zero init (re-done every launch: deterministic) ----------
__global__ void zero_kernel() {
    int i = blockIdx.x * blockDim.x + threadIdx.x;
    int stride = gridDim.x * blockDim.x;
    for (int j = i; j < M_*N_*H_; j += stride) g_denom[j] = 0.f;
    for (int j = i; j < M_*N_;    j += stride) g_deg[j]   = 0;
    if (i < M_) g_wsum[i] = 0.f;
}

// ---------------- generic 64x64 tiled fp32 GEMM ----------------------------
// MODE 0: feat[m] = h @ W[m]            (batched over blockIdx.z)
// MODE 1: hid = tanh(z @ sem_W1 + b1)   (single batch)
template<int MODE>
__global__ void gemm64(const float* __restrict__ Aext,
                       const float* __restrict__ Bext,
                       const float* __restrict__ biasv)
{
    constexpr int Mrows = (MODE == 0) ? N_      : M_*N_;
    constexpr int K     = (MODE == 0) ? IN_     : HD_;
    constexpr int Nc    = (MODE == 0) ? HD_     : HID_;

    const float* A = (MODE == 0) ? Aext : g_z;
    const float* B = (MODE == 0) ? (Bext + (size_t)blockIdx.z * IN_ * HD_) : Bext;
    float*       C = (MODE == 0) ? (g_feat + (size_t)blockIdx.z * N_ * HD_) : g_hid;

    __shared__ __align__(16) float As[32][64];   // [k][m]
    __shared__ __align__(16) float Bs[32][64];   // [k][n]

    int tid = threadIdx.x;            // 256 threads
    int tm = tid >> 4, tn = tid & 15; // 16x16, each 4x4 outputs
    int row0 = blockIdx.x * 64, col0 = blockIdx.y * 64;
    float acc[4][4] = {};

    for (int k0 = 0; k0 < K; k0 += 32) {
        int t2 = tid * 2;
#pragma unroll
        for (int i = 0; i < 2; i++) {           // A tile: 64 rows x 32 k
            int li = t2 + i;                    // 0..511 float4 slots
            int r  = li >> 3;
            int c4 = (li & 7) * 4;
            float4 v = make_float4(0.f, 0.f, 0.f, 0.f);
            int row = row0 + r;
            if (row < Mrows) v = *(const float4*)&A[(size_t)row * K + k0 + c4];
            As[c4 + 0][r] = v.x; As[c4 + 1][r] = v.y;
            As[c4 + 2][r] = v.z; As[c4 + 3][r] = v.w;
        }
#pragma unroll
        for (int i = 0; i < 2; i++) {           // B tile: 32 k x 64 cols
            int li = t2 + i;
            int kk = li >> 4;
            int c4 = (li & 15) * 4;
            *(float4*)&Bs[kk][c4] = *(const float4*)&B[(size_t)(k0 + kk) * Nc + col0 + c4];
        }
        __syncthreads();
#pragma unroll
        for (int k = 0; k < 32; k++) {
            float4 a = *(const float4*)&As[k][tm * 4];
            float4 b = *(const float4*)&Bs[k][tn * 4];
            acc[0][0] += a.x*b.x; acc[0][1] += a.x*b.y; acc[0][2] += a.x*b.z; acc[0][3] += a.x*b.w;
            acc[1][0] += a.y*b.x; acc[1][1] += a.y*b.y; acc[1][2] += a.y*b.z; acc[1][3] += a.y*b.w;
            acc[2][0] += a.z*b.x; acc[2][1] += a.z*b.y; acc[2][2] += a.z*b.z; acc[2][3] += a.z*b.w;
            acc[3][0] += a.w*b.x; acc[3][1] += a.w*b.y; acc[3][2] += a.w*b.z; acc[3][3] += a.w*b.w;
        }
        __syncthreads();
    }

#pragma unroll
    for (int i = 0; i < 4; i++) {
        int row = row0 + tm * 4 + i;
        if (row < Mrows) {
            float4 v;
            float x0 = acc[i][0], x1 = acc[i][1], x2 = acc[i][2], x3 = acc[i][3];
            if (MODE == 1) {
                int c = col0 + tn * 4;
                x0 = tanhf(x0 + biasv[c + 0]);
                x1 = tanhf(x1 + biasv[c + 1]);
                x2 = tanhf(x2 + biasv[c + 2]);
                x3 = tanhf(x3 + biasv[c + 3]);
            }
            v.x = x0; v.y = x1; v.z = x2; v.w = x3;
            *(float4*)&C[(size_t)row * Nc + col0 + tn * 4] = v;
        }
    }
}

// ---------------- el / er : per (m, node, head) dot over D ------------------
__global__ void eler_kernel(const float* __restrict__ attn_l,
                            const float* __restrict__ attn_r)
{
    int n = blockIdx.x, m = blockIdx.y;
    int h = threadIdx.x >> 5, lane = threadIdx.x & 31;
    const float* f  = &g_feat[((size_t)m * N_ + n) * HD_ + h * D_];
    const float* al = &attn_l[(m * H_ + h) * D_];
    const float* ar = &attn_r[(m * H_ + h) * D_];
    float v0 = f[lane], v1 = f[lane + 32];
    float sl = v0 * al[lane] + v1 * al[lane + 32];
    float sr = v0 * ar[lane] + v1 * ar[lane + 32];
#pragma unroll
    for (int o = 16; o; o >>= 1) {
        sl += __shfl_xor_sync(0xffffffffu, sl, o);
        sr += __shfl_xor_sync(0xffffffffu, sr, o);
    }
    if (lane == 0) {
        int idx = (m * N_ + n) * H_ + h;
        g_el[idx] = sl;
        g_er[idx] = sr;
    }
}

// ---------------- per-edge: exp scores, denom, degree hist ------------------
__global__ void edge_kernel(const int* __restrict__ src,
                            const int* __restrict__ dst)
{
    int idx = blockIdx.x * blockDim.x + threadIdx.x;
    if (idx >= M_ * E_) return;
    int m = idx / E_;
    int s = src[idx], d = dst[idx];
    atomicAdd(&g_deg[m * N_ + d], 1);
    float4 el4 = *(const float4*)&g_el[(size_t)(m * N_ + s) * H_];
    float4 er4 = *(const float4*)&g_er[(size_t)(m * N_ + d) * H_];
    float e0 = el4.x + er4.x, e1 = el4.y + er4.y, e2 = el4.z + er4.z, e3 = el4.w + er4.w;
    e0 = e0 > 0.f ? e0 : NEG_SLOPE * e0;
    e1 = e1 > 0.f ? e1 : NEG_SLOPE * e1;
    e2 = e2 > 0.f ? e2 : NEG_SLOPE * e2;
    e3 = e3 > 0.f ? e3 : NEG_SLOPE * e3;
    float4 ee;
    ee.x = __expf(e0); ee.y = __expf(e1); ee.z = __expf(e2); ee.w = __expf(e3);
    *(float4*)&g_ee[(size_t)idx * H_] = ee;
    float* dn = &g_denom[(size_t)(m * N_ + d) * H_];
    atomicAdd(&dn[0], ee.x);
    atomicAdd(&dn[1], ee.y);
    atomicAdd(&dn[2], ee.z);
    atomicAdd(&dn[3], ee.w);
}

// ---------------- exclusive scan of degrees -> rowptr / cursor --------------
__global__ void scan_kernel()
{
    __shared__ int s[1024];
    int m = blockIdx.x;
    int t = threadIdx.x;
    const int chunk = (N_ + 1023) / 1024;   // 20
    int start = t * chunk;
    int sum = 0;
    for (int i = 0; i < chunk; i++) {
        int j = start + i;
        if (j < N_) sum += g_deg[m * N_ + j];
    }
    s[t] = sum;
    __syncthreads();
    for (int off = 1; off < 1024; off <<= 1) {
        int v = (t >= off) ? s[t - off] : 0;
        __syncthreads();
        s[t] += v;
        __syncthreads();
    }
    int run = (t == 0) ? 0 : s[t - 1];       // exclusive prefix
    for (int i = 0; i < chunk; i++) {
        int j = start + i;
        if (j < N_) {
            g_rowptr[m * (N_ + 1) + j] = run;
            g_cursor[m * N_ + j] = run;
            run += g_deg[m * N_ + j];
        }
    }
    if (t == 1023) g_rowptr[m * (N_ + 1) + N_] = run;  // == E_
}

// ---------------- scatter edge ids by destination ---------------------------
__global__ void scatter_kernel(const int* __restrict__ dst)
{
    int idx = blockIdx.x * blockDim.x + threadIdx.x;
    if (idx >= M_ * E_) return;
    int m = idx / E_;
    int e = idx - m * E_;
    int d = dst[idx];
    int pos = atomicAdd(&g_cursor[m * N_ + d], 1);
    g_eidx[m * E_ + pos] = e;
}

// ---------------- atomic-free aggregation: warp per (m,n,head) --------------
__global__ void agg_kernel(const int* __restrict__ src,
                           const float* __restrict__ bias)
{
    int n = blockIdx.x, m = blockIdx.y;
    int h = threadIdx.x >> 5, lane = threadIdx.x & 31;
    int beg = g_rowptr[m * (N_ + 1) + n];
    int end = g_rowptr[m * (N_ + 1) + n + 1];
    float acc0 = 0.f, acc1 = 0.f;
    const int* eix = &g_eidx[(size_t)m * E_];
    const int* srcm = &src[(size_t)m * E_];
    for (int i = beg; i < end; i++) {
        int e = eix[i];
        int s = srcm[e];
        float a = g_ee[((size_t)m * E_ + e) * H_ + h];
        const float* f = &g_feat[((size_t)m * N_ + s) * HD_ + h * D_];
        acc0 += a * f[lane];
        acc1 += a * f[lane + 32];
    }
    float inv = 1.f / fmaxf(g_denom[(size_t)(m * N_ + n) * H_ + h], 1e-9f);
    float b0 = bias[m * HD_ + h * D_ + lane];
    float b1 = bias[m * HD_ + h * D_ + lane + 32];
    float* zp = &g_z[((size_t)m * N_ + n) * HD_ + h * D_];
    zp[lane]      = acc0 * inv + b0;
    zp[lane + 32] = acc1 * inv + b1;
}

// ---------------- semantic score: hid @ sem_W2 -> per-metapath sum ----------
__global__ void wscore_kernel(const float* __restrict__ sem_W2)
{
    int gw = (blockIdx.x * blockDim.x + threadIdx.x) >> 5;
    int lane = threadIdx.x & 31;
    if (gw >= M_ * N_) return;
    const float* hp = &g_hid[(size_t)gw * HID_];
    float sum = hp[lane] * sem_W2[lane] +
                hp[lane + 32] * sem_W2[lane + 32] +
                hp[lane + 64] * sem_W2[lane + 64] +
                hp[lane + 96] * sem_W2[lane + 96];
#pragma unroll
    for (int o = 16; o; o >>= 1) sum += __shfl_xor_sync(0xffffffffu, sum, o);
    if (lane == 0) {
        int m = gw / N_;
        atomicAdd(&g_wsum[m], sum);
    }
}

// ---------------- beta = softmax(mean) --------------------------------------
__global__ void beta_kernel()
{
    float w0 = g_wsum[0] / (float)N_;
    float w1 = g_wsum[1] / (float)N_;
    float w2 = g_wsum[2] / (float)N_;
    float mx = fmaxf(w0, fmaxf(w1, w2));
    float x0 = expf(w0 - mx), x1 = expf(w1 - mx), x2 = expf(w2 - mx);
    float s = x0 + x1 + x2;
    g_beta[0] = x0 / s;
    g_beta[1] = x1 / s;
    g_beta[2] = x2 / s;
}

// ---------------- out = sum_m beta[m] * z[m] --------------------------------
__global__ void final_kernel(float* __restrict__ out)
{
    int idx = blockIdx.x * blockDim.x + threadIdx.x;
    if (idx >= N_ * HD_ / 4) return;
    float b0 = g_beta[0], b1 = g_beta[1], b2 = g_beta[2];
    float4 z0 = *(const float4*)&g_z[(size_t)idx * 4];
    float4 z1 = *(const float4*)&g_z[(size_t)N_ * HD_ + idx * 4];
    float4 z2 = *(const float4*)&g_z[(size_t)2 * N_ * HD_ + idx * 4];
    float4 o;
    o.x = b0 * z0.x + b1 * z1.x + b2 * z2.x;
    o.y = b0 * z0.y + b1 * z1.y + b2 * z2.y;
    o.z = b0 * z0.z + b1 * z1.z + b2 * z2.z;
    o.w = b0 * z0.w + b1 * z1.w + b2 * z2.w;
    *(float4*)&out[(size_t)idx * 4] = o;
}

// ---------------- launcher --------------------------------------------------
extern "C" void kernel_launch(void* const* d_in, const int* in_sizes, int n_in,
                              void* d_out, int out_size)
{
    const float* h       = (const float*)d_in[0];
    const int*   src     = (const int*)  d_in[1];
    const int*   dst     = (const int*)  d_in[2];
    const float* W       = (const float*)d_in[3];
    const float* attn_l  = (const float*)d_in[4];
    const float* attn_r  = (const float*)d_in[5];
    const float* bias    = (const float*)d_in[6];
    const float* sem_W1  = (const float*)d_in[7];
    const float* sem_b1  = (const float*)d_in[8];
    const float* sem_W2  = (const float*)d_in[9];
    float* out = (float*)d_out;
    (void)in_sizes; (void)n_in; (void)out_size;

    zero_kernel<<<240, 256>>>();

    // feat[m] = h @ W[m]
    {
        dim3 g((N_ + 63) / 64, HD_ / 64, M_);
        gemm64<0><<<g, 256>>>(h, W, nullptr);
    }

    // el / er
    {
        dim3 g(N_, M_);
        eler_kernel<<<g, 128>>>(attn_l, attn_r);
    }

    // per-edge scores + denom + degree histogram
    edge_kernel<<<(M_ * E_ + 255) / 256, 256>>>(src, dst);

    // CSR build
    scan_kernel<<<M_, 1024>>>();
    scatter_kernel<<<(M_ * E_ + 255) / 256, 256>>>(dst);

    // aggregation -> z (GAT output + bias)
    {
        dim3 g(N_, M_);
        agg_kernel<<<g, 128>>>(src, bias);
    }

    // hid = tanh(z @ sem_W1 + b1)
    {
        dim3 g((M_ * N_ + 63) / 64, HID_ / 64, 1);
        gemm64<1><<<g, 256>>>(nullptr, sem_W1, sem_b1);
    }

    // semantic scores -> per-metapath sums -> beta
    wscore_kernel<<<(M_ * N_ * 32 + 255) / 256, 256>>>(sem_W2);
    beta_kernel<<<1, 1>>>();

    // out = sum_m beta[m] * z[m]
    final_kernel<<<(N_ * HD_ / 4 + 255) / 256, 256>>>(out);
}

// round 2
// speedup vs baseline: 2.4494x; 2.4494x over previous
#include <cuda_runtime.h>
#include <math.h>
#include <stdint.h>

#define N_   20000
#define E_   320000
#define M_   3
#define IN_  128
#define H_   4
#define D_   64
#define HD_  256
#define HID_ 128
#define NEG_SLOPE 0.2f

// ---------------- scratch (device globals: allocation-free) ----------------
__device__ __align__(16) float g_feat[M_*N_*HD_];   // [m][n][hd]
__device__ __align__(16) float g_z   [M_*N_*HD_];   // [m][n][hd]
__device__ __align__(16) float g_el  [M_*N_*H_];
__device__ __align__(16) float g_er  [M_*N_*H_];
__device__ __align__(16) float g_ee2 [M_*E_*H_];    // CSR-ordered exp scores
__device__ int   g_esrc [M_*E_];                     // CSR-ordered src ids
__device__ int   g_deg   [M_*N_];
__device__ int   g_rowptr[M_*(N_+1)];
__device__ int   g_cursor[M_*N_];
__device__ float g_wsum  [M_];
__device__ float g_beta  [M_];

// ---------------- helpers ---------------------------------------------------
__device__ __forceinline__ float to_tf32(float x) {
    unsigned u;
    asm("cvt.rna.tf32.f32 %0, %1;" : "=r"(u) : "f"(x));
    return __uint_as_float(u);
}
__device__ __forceinline__ float tanh_fast(float x) {
    float y;
    asm("tanh.approx.f32 %0, %1;" : "=f"(y) : "f"(x));
    return y;
}
__device__ __forceinline__ void mma_tf32(float (&d)[4],
    unsigned a0, unsigned a1, unsigned a2, unsigned a3,
    unsigned b0, unsigned b1)
{
    asm volatile(
        "mma.sync.aligned.m16n8k8.row.col.f32.tf32.tf32.f32 "
        "{%0,%1,%2,%3}, {%4,%5,%6,%7}, {%8,%9}, {%0,%1,%2,%3};\n"
        : "+f"(d[0]), "+f"(d[1]), "+f"(d[2]), "+f"(d[3])
        : "r"(a0), "r"(a1), "r"(a2), "r"(a3), "r"(b0), "r"(b1));
}

// ---------------- zero init -------------------------------------------------
__global__ void zero_kernel() {
    int i = blockIdx.x * blockDim.x + threadIdx.x;
    int stride = gridDim.x * blockDim.x;
    for (int j = i; j < M_*N_; j += stride) g_deg[j] = 0;
    if (i < M_) g_wsum[i] = 0.f;
}

// ---------------- tf32 tensor-core GEMM ------------------------------------
// MODE 0: feat[m] = h @ W[m]  (batched over blockIdx.z) + fused el/er
// MODE 1: wsum[m] += sum over rows of tanh(z@W1+b1)@W2   (nothing stored)
#define BM 128
#define BN 128
#define BK 16
#define SSTRIDE 136

template<int MODE>
__global__ void __launch_bounds__(256) gemm_tc(
    const float* __restrict__ Aext,
    const float* __restrict__ Bext,
    const float* __restrict__ attn_l,
    const float* __restrict__ attn_r,
    const float* __restrict__ b1v,
    const float* __restrict__ W2)
{
    constexpr int Mtot = (MODE == 0) ? N_  : M_*N_;
    constexpr int K    = (MODE == 0) ? IN_ : HD_;
    constexpr int Nc   = (MODE == 0) ? HD_ : HID_;
    constexpr int KT   = K / BK;

    const float* A = (MODE == 0) ? Aext : g_z;
    const float* B = (MODE == 0) ? (Bext + (size_t)blockIdx.z * IN_ * HD_) : Bext;

    __shared__ __align__(16) float As[2][BK][SSTRIDE];
    __shared__ __align__(16) float Bs[2][BK][SSTRIDE];
    __shared__ float s_wsum[M_];

    int tid    = threadIdx.x;
    int warp   = tid >> 5, lane = tid & 31;
    int warp_m = warp >> 1, warp_n = warp & 1;
    int gid    = lane >> 2, tg = lane & 3;
    int row0   = blockIdx.x * BM, col0 = blockIdx.y * BN;

    if (MODE == 1 && tid < M_) s_wsum[tid] = 0.f;

    float acc[2][8][4];
#pragma unroll
    for (int a = 0; a < 2; a++)
#pragma unroll
        for (int b = 0; b < 8; b++)
#pragma unroll
            for (int c = 0; c < 4; c++) acc[a][b][c] = 0.f;

    float4 ra[2], rb[2];
    const float4 z4 = make_float4(0.f, 0.f, 0.f, 0.f);

    // --- prologue: load tile 0 ---
#pragma unroll
    for (int i = 0; i < 2; i++) {
        int li = tid * 2 + i;
        { int mA = li >> 2, k4 = (li & 3) * 4;
          int row = row0 + mA;
          ra[i] = (row < Mtot) ? *(const float4*)&A[(size_t)row * K + k4] : z4; }
        { int kB = li >> 5, n4 = (li & 31) * 4;
          rb[i] = *(const float4*)&B[(size_t)kB * Nc + col0 + n4]; }
    }
#pragma unroll
    for (int i = 0; i < 2; i++) {
        int li = tid * 2 + i;
        { int mA = li >> 2, k4 = (li & 3) * 4;
          As[0][k4 + 0][mA] = to_tf32(ra[i].x);
          As[0][k4 + 1][mA] = to_tf32(ra[i].y);
          As[0][k4 + 2][mA] = to_tf32(ra[i].z);
          As[0][k4 + 3][mA] = to_tf32(ra[i].w); }
        { int kB = li >> 5, n4 = (li & 31) * 4;
          float4 t;
          t.x = to_tf32(rb[i].x); t.y = to_tf32(rb[i].y);
          t.z = to_tf32(rb[i].z); t.w = to_tf32(rb[i].w);
          *(float4*)&Bs[0][kB][n4] = t; }
    }
    __syncthreads();

    for (int kt = 0; kt < KT; kt++) {
        int cur = kt & 1;
        if (kt + 1 < KT) {
#pragma unroll
            for (int i = 0; i < 2; i++) {
                int li = tid * 2 + i;
                { int mA = li >> 2, k4 = (li & 3) * 4;
                  int row = row0 + mA;
                  ra[i] = (row < Mtot)
                      ? *(const float4*)&A[(size_t)row * K + (kt + 1) * BK + k4] : z4; }
                { int kB = li >> 5, n4 = (li & 31) * 4;
                  rb[i] = *(const float4*)&B[(size_t)((kt + 1) * BK + kB) * Nc + col0 + n4]; }
            }
        }
        // --- compute current buffer ---
#pragma unroll
        for (int kc = 0; kc < BK; kc += 8) {
            unsigned afr[2][4];
#pragma unroll
            for (int mi = 0; mi < 2; mi++) {
                int mb = warp_m * 32 + mi * 16;
                afr[mi][0] = __float_as_uint(As[cur][kc + tg    ][mb + gid]);
                afr[mi][1] = __float_as_uint(As[cur][kc + tg    ][mb + gid + 8]);
                afr[mi][2] = __float_as_uint(As[cur][kc + tg + 4][mb + gid]);
                afr[mi][3] = __float_as_uint(As[cur][kc + tg + 4][mb + gid + 8]);
            }
#pragma unroll
            for (int nj = 0; nj < 8; nj++) {
                int nb = warp_n * 64 + nj * 8 + gid;
                unsigned b0 = __float_as_uint(Bs[cur][kc + tg    ][nb]);
                unsigned b1 = __float_as_uint(Bs[cur][kc + tg + 4][nb]);
                mma_tf32(acc[0][nj], afr[0][0], afr[0][1], afr[0][2], afr[0][3], b0, b1);
                mma_tf32(acc[1][nj], afr[1][0], afr[1][1], afr[1][2], afr[1][3], b0, b1);
            }
        }
        if (kt + 1 < KT) {
            int nxt = (kt + 1) & 1;
#pragma unroll
            for (int i = 0; i < 2; i++) {
                int li = tid * 2 + i;
                { int mA = li >> 2, k4 = (li & 3) * 4;
                  As[nxt][k4 + 0][mA] = to_tf32(ra[i].x);
                  As[nxt][k4 + 1][mA] = to_tf32(ra[i].y);
                  As[nxt][k4 + 2][mA] = to_tf32(ra[i].z);
                  As[nxt][k4 + 3][mA] = to_tf32(ra[i].w); }
                { int kB = li >> 5, n4 = (li & 31) * 4;
                  float4 t;
                  t.x = to_tf32(rb[i].x); t.y = to_tf32(rb[i].y);
                  t.z = to_tf32(rb[i].z); t.w = to_tf32(rb[i].w);
                  *(float4*)&Bs[nxt][kB][n4] = t; }
            }
            __syncthreads();
        }
    }

    // ---------------- epilogues ----------------
    if (MODE == 0) {
        float* featm = g_feat + (size_t)blockIdx.z * N_ * HD_;
        int h = blockIdx.y * 2 + warp_n;
        const float* al = attn_l + ((size_t)blockIdx.z * H_ + h) * D_;
        const float* ar = attn_r + ((size_t)blockIdx.z * H_ + h) * D_;
        float sl[4] = {0.f, 0.f, 0.f, 0.f};
        float sr[4] = {0.f, 0.f, 0.f, 0.f};
#pragma unroll
        for (int nj = 0; nj < 8; nj++) {
            int ch = nj * 8 + tg * 2;
            float al0 = al[ch], al1 = al[ch + 1];
            float ar0 = ar[ch], ar1 = ar[ch + 1];
            int col = col0 + warp_n * 64 + ch;
#pragma unroll
            for (int mi = 0; mi < 2; mi++) {
                float c0 = acc[mi][nj][0], c1 = acc[mi][nj][1];
                float c2 = acc[mi][nj][2], c3 = acc[mi][nj][3];
                sl[mi * 2 + 0] += c0 * al0 + c1 * al1;
                sr[mi * 2 + 0] += c0 * ar0 + c1 * ar1;
                sl[mi * 2 + 1] += c2 * al0 + c3 * al1;
                sr[mi * 2 + 1] += c2 * ar0 + c3 * ar1;
                int row = row0 + warp_m * 32 + mi * 16 + gid;
                if (row < N_)
                    *(float2*)&featm[(size_t)row * HD_ + col] = make_float2(c0, c1);
                if (row + 8 < N_)
                    *(float2*)&featm[(size_t)(row + 8) * HD_ + col] = make_float2(c2, c3);
            }
        }
#pragma unroll
        for (int s = 0; s < 4; s++) {
            sl[s] += __shfl_xor_sync(0xffffffffu, sl[s], 1);
            sl[s] += __shfl_xor_sync(0xffffffffu, sl[s], 2);
            sr[s] += __shfl_xor_sync(0xffffffffu, sr[s], 1);
            sr[s] += __shfl_xor_sync(0xffffffffu, sr[s], 2);
        }
        if (tg == 0) {
#pragma unroll
            for (int mi = 0; mi < 2; mi++)
#pragma unroll
                for (int rh = 0; rh < 2; rh++) {
                    int row = row0 + warp_m * 32 + mi * 16 + gid + rh * 8;
                    if (row < N_) {
                        int o = ((int)blockIdx.z * N_ + row) * H_ + h;
                        g_el[o] = sl[mi * 2 + rh];
                        g_er[o] = sr[mi * 2 + rh];
                    }
                }
        }
    } else {
        float s[4] = {0.f, 0.f, 0.f, 0.f};
#pragma unroll
        for (int nj = 0; nj < 8; nj++) {
            int col = col0 + warp_n * 64 + nj * 8 + tg * 2;
            float w20 = W2[col], w21 = W2[col + 1];
            float bb0 = b1v[col], bb1 = b1v[col + 1];
#pragma unroll
            for (int mi = 0; mi < 2; mi++) {
                float x0 = tanh_fast(acc[mi][nj][0] + bb0);
                float x1 = tanh_fast(acc[mi][nj][1] + bb1);
                float x2 = tanh_fast(acc[mi][nj][2] + bb0);
                float x3 = tanh_fast(acc[mi][nj][3] + bb1);
                s[mi * 2 + 0] += x0 * w20 + x1 * w21;
                s[mi * 2 + 1] += x2 * w20 + x3 * w21;
            }
        }
#pragma unroll
        for (int i = 0; i < 4; i++) {
            s[i] += __shfl_xor_sync(0xffffffffu, s[i], 1);
            s[i] += __shfl_xor_sync(0xffffffffu, s[i], 2);
        }
        __syncthreads();   // s_wsum init visible (set at kernel start)
        if (tg == 0) {
#pragma unroll
            for (int mi = 0; mi < 2; mi++)
#pragma unroll
                for (int rh = 0; rh < 2; rh++) {
                    int row = row0 + warp_m * 32 + mi * 16 + gid + rh * 8;
                    if (row < Mtot) atomicAdd(&s_wsum[row / N_], s[mi * 2 + rh]);
                }
        }
        __syncthreads();
        if (tid < M_) atomicAdd(&g_wsum[tid], s_wsum[tid]);
    }
}

// ---------------- degree histogram ------------------------------------------
__global__ void deg_kernel(const int* __restrict__ dst) {
    int idx = blockIdx.x * blockDim.x + threadIdx.x;
    if (idx >= M_ * E_) return;
    int m = idx / E_;
    atomicAdd(&g_deg[m * N_ + dst[idx]], 1);
}

// ---------------- exclusive scan -> rowptr / cursor -------------------------
__global__ void scan_kernel() {
    __shared__ int s[1024];
    int m = blockIdx.x;
    int t = threadIdx.x;
    const int chunk = (N_ + 1023) / 1024;
    int start = t * chunk;
    int sum = 0;
    for (int i = 0; i < chunk; i++) {
        int j = start + i;
        if (j < N_) sum += g_deg[m * N_ + j];
    }
    s[t] = sum;
    __syncthreads();
    for (int off = 1; off < 1024; off <<= 1) {
        int v = (t >= off) ? s[t - off] : 0;
        __syncthreads();
        s[t] += v;
        __syncthreads();
    }
    int run = (t == 0) ? 0 : s[t - 1];
    for (int i = 0; i < chunk; i++) {
        int j = start + i;
        if (j < N_) {
            g_rowptr[m * (N_ + 1) + j] = run;
            g_cursor[m * N_ + j] = run;
            run += g_deg[m * N_ + j];
        }
    }
    if (t == 1023) g_rowptr[m * (N_ + 1) + N_] = run;
}

// ---------------- edge pass: scores + CSR scatter ---------------------------
__global__ void edge_scatter_kernel(const int* __restrict__ src,
                                    const int* __restrict__ dst)
{
    int idx = blockIdx.x * blockDim.x + threadIdx.x;
    if (idx >= M_ * E_) return;
    int m = idx / E_;
    int s = src[idx], d = dst[idx];
    float4 el4 = *(const float4*)&g_el[(size_t)(m * N_ + s) * H_];
    float4 er4 = *(const float4*)&g_er[(size_t)(m * N_ + d) * H_];
    float e0 = el4.x + er4.x, e1 = el4.y + er4.y;
    float e2 = el4.z + er4.z, e3 = el4.w + er4.w;
    e0 = e0 > 0.f ? e0 : NEG_SLOPE * e0;
    e1 = e1 > 0.f ? e1 : NEG_SLOPE * e1;
    e2 = e2 > 0.f ? e2 : NEG_SLOPE * e2;
    e3 = e3 > 0.f ? e3 : NEG_SLOPE * e3;
    float4 ee;
    ee.x = __expf(e0); ee.y = __expf(e1); ee.z = __expf(e2); ee.w = __expf(e3);
    int pos = atomicAdd(&g_cursor[m * N_ + d], 1);
    g_esrc[(size_t)m * E_ + pos] = s;
    *(float4*)&g_ee2[((size_t)m * E_ + pos) * 4] = ee;
}

// ---------------- aggregation: 1 warp per node, CSR sequential --------------
__global__ void __launch_bounds__(256) agg_kernel(int m, const float* __restrict__ bias)
{
    int warp = threadIdx.x >> 5, lane = threadIdx.x & 31;
    int n = blockIdx.x * 8 + warp;            // N_ % 8 == 0
    const float* featm = g_feat + (size_t)m * N_ * HD_;
    const int*   rp    = g_rowptr + m * (N_ + 1);
    const int*   esrc  = g_esrc + (size_t)m * E_;
    const float* ee2   = g_ee2 + (size_t)m * E_ * 4;

    int beg = rp[n], end = rp[n + 1];
    int h0 = lane >> 4;                       // head for cols [0,128): 0/1
    float4 a0 = make_float4(0.f, 0.f, 0.f, 0.f);
    float4 a1 = make_float4(0.f, 0.f, 0.f, 0.f);
    float d0 = 0.f, d1 = 0.f;

    int i = beg;
    for (; i + 1 < end; i += 2) {
        int s0 = esrc[i], s1 = esrc[i + 1];
        float w0 = ee2[i * 4 + h0],       x0 = ee2[i * 4 + 2 + h0];
        float w1 = ee2[(i + 1) * 4 + h0], x1 = ee2[(i + 1) * 4 + 2 + h0];
        const float4* f0 = (const float4*)(featm + (size_t)s0 * HD_);
        const float4* f1 = (const float4*)(featm + (size_t)s1 * HD_);
        float4 u0 = f0[lane], v0 = f0[lane + 32];
        float4 u1 = f1[lane], v1 = f1[lane + 32];
        a0.x += w0 * u0.x + w1 * u1.x; a0.y += w0 * u0.y + w1 * u1.y;
        a0.z += w0 * u0.z + w1 * u1.z; a0.w += w0 * u0.w + w1 * u1.w;
        a1.x += x0 * v0.x + x1 * v1.x; a1.y += x0 * v0.y + x1 * v1.y;
        a1.z += x0 * v0.z + x1 * v1.z; a1.w += x0 * v0.w + x1 * v1.w;
        d0 += w0 + w1; d1 += x0 + x1;
    }
    if (i < end) {
        int s0 = esrc[i];
        float w0 = ee2[i * 4 + h0], x0 = ee2[i * 4 + 2 + h0];
        const float4* f0 = (const float4*)(featm + (size_t)s0 * HD_);
        float4 u0 = f0[lane], v0 = f0[lane + 32];
        a0.x += w0 * u0.x; a0.y += w0 * u0.y; a0.z += w0 * u0.z; a0.w += w0 * u0.w;
        a1.x += x0 * v0.x; a1.y += x0 * v0.y; a1.z += x0 * v0.z; a1.w += x0 * v0.w;
        d0 += w0; d1 += x0;
    }

    float inv0 = 1.f / fmaxf(d0, 1e-9f);
    float inv1 = 1.f / fmaxf(d1, 1e-9f);
    const float4* b0 = (const float4*)(bias + (size_t)m * HD_);
    float4 bb0 = b0[lane], bb1 = b0[lane + 32];
    float4 o0, o1;
    o0.x = a0.x * inv0 + bb0.x; o0.y = a0.y * inv0 + bb0.y;
    o0.z = a0.z * inv0 + bb0.z; o0.w = a0.w * inv0 + bb0.w;
    o1.x = a1.x * inv1 + bb1.x; o1.y = a1.y * inv1 + bb1.y;
    o1.z = a1.z * inv1 + bb1.z; o1.w = a1.w * inv1 + bb1.w;
    float4* zp = (float4*)(g_z + ((size_t)m * N_ + n) * HD_);
    zp[lane]      = o0;
    zp[lane + 32] = o1;
}

// ---------------- beta = softmax(mean) --------------------------------------
__global__ void beta_kernel() {
    float w0 = g_wsum[0] / (float)N_;
    float w1 = g_wsum[1] / (float)N_;
    float w2 = g_wsum[2] / (float)N_;
    float mx = fmaxf(w0, fmaxf(w1, w2));
    float x0 = expf(w0 - mx), x1 = expf(w1 - mx), x2 = expf(w2 - mx);
    float s = x0 + x1 + x2;
    g_beta[0] = x0 / s;
    g_beta[1] = x1 / s;
    g_beta[2] = x2 / s;
}

// ---------------- out = sum_m beta[m] * z[m] --------------------------------
__global__ void final_kernel(float* __restrict__ out) {
    int idx = blockIdx.x * blockDim.x + threadIdx.x;
    if (idx >= N_ * HD_ / 4) return;
    float b0 = g_beta[0], b1 = g_beta[1], b2 = g_beta[2];
    float4 z0 = *(const float4*)&g_z[(size_t)idx * 4];
    float4 z1 = *(const float4*)&g_z[(size_t)N_ * HD_ + idx * 4];
    float4 z2 = *(const float4*)&g_z[(size_t)2 * N_ * HD_ + idx * 4];
    float4 o;
    o.x = b0 * z0.x + b1 * z1.x + b2 * z2.x;
    o.y = b0 * z0.y + b1 * z1.y + b2 * z2.y;
    o.z = b0 * z0.z + b1 * z1.z + b2 * z2.z;
    o.w = b0 * z0.w + b1 * z1.w + b2 * z2.w;
    *(float4*)&out[(size_t)idx * 4] = o;
}

// ---------------- launcher --------------------------------------------------
extern "C" void kernel_launch(void* const* d_in, const int* in_sizes, int n_in,
                              void* d_out, int out_size)
{
    const float* h       = (const float*)d_in[0];
    const int*   src     = (const int*)  d_in[1];
    const int*   dst     = (const int*)  d_in[2];
    const float* W       = (const float*)d_in[3];
    const float* attn_l  = (const float*)d_in[4];
    const float* attn_r  = (const float*)d_in[5];
    const float* bias    = (const float*)d_in[6];
    const float* sem_W1  = (const float*)d_in[7];
    const float* sem_b1  = (const float*)d_in[8];
    const float* sem_W2  = (const float*)d_in[9];
    float* out = (float*)d_out;
    (void)in_sizes; (void)n_in; (void)out_size;

    zero_kernel<<<240, 256>>>();
    deg_kernel<<<(M_ * E_ + 255) / 256, 256>>>(dst);
    scan_kernel<<<M_, 1024>>>();

    // feat = h @ W  (+ fused el/er)
    {
        dim3 g((N_ + BM - 1) / BM, HD_ / BN, M_);
        gemm_tc<0><<<g, 256>>>(h, W, attn_l, attn_r, nullptr, nullptr);
    }

    // per-edge scores -> CSR-ordered esrc/ee
    edge_scatter_kernel<<<(M_ * E_ + 255) / 256, 256>>>(src, dst);

    // aggregation (per metapath so feat slice stays L2-hot)
    for (int m = 0; m < M_; m++)
        agg_kernel<<<N_ / 8, 256>>>(m, bias);

    // semantic GEMM with fused tanh -> W2 -> wsum
    {
        dim3 g((M_ * N_ + BM - 1) / BM, HID_ / BN, 1);
        gemm_tc<1><<<g, 256>>>(nullptr, sem_W1, nullptr, nullptr, sem_b1, sem_W2);
    }

    beta_kernel<<<1, 1>>>();
    final_kernel<<<(N_ * HD_ / 4 + 255) / 256, 256>>>(out);
}